// round 12
// baseline (speedup 1.0000x reference)
#include <cuda_runtime.h>
#include <math.h>
#include <stdint.h>

#define B 4
#define N 2048
#define M 2048
#define C 512
#define H 4
#define DV 128
#define DQK 256

// scratch: plain fp32 coalesced globals (verified layout), V^T sigma tiles
__device__ __align__(16) float    g_qn[B * H * N * DQK];   // 32 MB
__device__ __align__(16) float    g_kn[B * H * M * DQK];   // 32 MB
__device__ __align__(16) float    g_o [B * N * C];         // 16 MB
__device__ __align__(16) uint32_t g_vt[B * H * M * DV];    // V^T tiles, sigma tf32

// ============================================================================
// tf32 mma.sync helpers
// ============================================================================
__device__ __forceinline__ uint32_t f2tf32(float f) {
    uint32_t u;
    asm("cvt.rna.tf32.f32 %0, %1;" : "=r"(u) : "f"(f));
    return u;
}
__device__ __forceinline__ uint4 cvt4(float4 v) {
    uint4 u;
    u.x = f2tf32(v.x); u.y = f2tf32(v.y); u.z = f2tf32(v.z); u.w = f2tf32(v.w);
    return u;
}
__device__ __forceinline__ void mma_tf32(float* c,
                                         uint32_t a0, uint32_t a1, uint32_t a2, uint32_t a3,
                                         uint32_t b0, uint32_t b1) {
    asm volatile(
        "mma.sync.aligned.m16n8k8.row.col.f32.tf32.tf32.f32 "
        "{%0,%1,%2,%3}, {%4,%5,%6,%7}, {%8,%9}, {%0,%1,%2,%3};"
        : "+f"(c[0]), "+f"(c[1]), "+f"(c[2]), "+f"(c[3])
        : "r"(a0), "r"(a1), "r"(a2), "r"(a3), "r"(b0), "r"(b1));
}

// sigma permutation within each 8-block of k-indices: positions [j0,j4,j1,j5,j2,j6,j3,j7]
// -> mma k-pair (k, k+4) is one contiguous uint2 at offset 2*tg.
// C-fragment col 2*tg lands at smap(tg) = (tg>>1)+(tg&1)*4; col 2*tg+1 at smap+2.

// interleave two float4 (cols j0..j3 and j4..j7) into sigma order, vectorized
__device__ __forceinline__ void st_sigma8(uint32_t* dst, float4 v0, float4 v1) {
    uint4 A, Bv;
    A.x  = f2tf32(v0.x); A.y  = f2tf32(v1.x); A.z  = f2tf32(v0.y); A.w  = f2tf32(v1.y);
    Bv.x = f2tf32(v0.z); Bv.y = f2tf32(v1.z); Bv.z = f2tf32(v0.w); Bv.w = f2tf32(v1.w);
    *(uint4*)(dst)     = A;
    *(uint4*)(dst + 4) = Bv;
}

// ---------------------------------------------------------------------------
// Pre-pass: V^T tiles. g_vt[((b*H+h)*32+mt)*128 + d][64 keys, sigma] (tf32)
// (verified in R6)
// ---------------------------------------------------------------------------
__global__ __launch_bounds__(128) void v_arrange_kernel(const float* __restrict__ ctx)
{
    const int bm = blockIdx.x;             // b*M + m
    const int b = bm >> 11, m = bm & 2047;
    const int i = threadIdx.x;
    const int h = i >> 5, d4 = (i & 31) * 4;
    float4 v = *(const float4*)(ctx + (size_t)bm * C + h * DV + d4);
    const int mt = m >> 6, ml = m & 63;
    const int pos = ((ml >> 3) << 3) + ((ml & 3) * 2 + ((ml >> 2) & 1));
    uint32_t* base = g_vt + ((size_t)((b * H + h) * 32 + mt) * DV) * 64;
    base[(size_t)(d4 + 0) * 64 + pos] = f2tf32(v.x);
    base[(size_t)(d4 + 1) * 64 + pos] = f2tf32(v.y);
    base[(size_t)(d4 + 2) * 64 + pos] = f2tf32(v.z);
    base[(size_t)(d4 + 3) * 64 + pos] = f2tf32(v.w);
}

// ---------------------------------------------------------------------------
// Kernel 1: fused QKV projection + per-head L2 norm * radius, tf32 mma.
// (unchanged from R10 — verified 184.6 us)
// ---------------------------------------------------------------------------
#define QKV_XS   0                    // 64 x 68 u32
#define QKV_WS   (64 * 68)            // 256 x 68 u32
#define QKV_SS   (QKV_WS + 256 * 68)  // 2 x 64 floats
#define QKV_SMEM ((QKV_SS + 128) * 4)

__global__ __launch_bounds__(256) void qkv_mma_kernel(
    const float* __restrict__ x, const float* __restrict__ ctx,
    const float* __restrict__ Wqkv, const float* __restrict__ radius)
{
    extern __shared__ float sm[];
    uint32_t* Xu = (uint32_t*)(sm + QKV_XS);
    uint32_t* Wu = (uint32_t*)(sm + QKV_WS);
    float* ssPart = sm + QKV_SS;

    const float* src = (blockIdx.z == 0) ? x : ctx;
    float* dst = (blockIdx.z == 0) ? g_qn : g_kn;
    const int h  = blockIdx.y;
    const int r0 = blockIdx.x * 64;
    const int tid = threadIdx.x;
    const int wid = tid >> 5;
    const int lane = tid & 31;
    const int wr = wid & 3;
    const int wc = wid >> 2;
    const int qr = wr * 16 + (lane >> 2);
    const int tg = lane & 3;

    float acc[16][4];
#pragma unroll
    for (int i = 0; i < 16; i++)
#pragma unroll
        for (int j = 0; j < 4; j++) acc[i][j] = 0.f;

    for (int kc = 0; kc < 8; kc++) {
#pragma unroll
        for (int t = 0; t < 4; t++) {
            int i = tid + t * 256;
            int r = i >> 4, cc = (i & 15) * 4;
            float4 v = *(const float4*)(src + (size_t)(r0 + r) * C + kc * 64 + cc);
            *(uint4*)(Xu + r * 68 + cc) = cvt4(v);
        }
#pragma unroll
        for (int t = 0; t < 16; t++) {
            int i = tid + t * 256;
            int r = i >> 4, cc = (i & 15) * 4;
            float4 v = *(const float4*)(Wqkv + (size_t)(h * 256 + r) * C + kc * 64 + cc);
            *(uint4*)(Wu + r * 68 + cc) = cvt4(v);
        }
        __syncthreads();

#pragma unroll
        for (int ks = 0; ks < 8; ks++) {
            const int c = ks * 8 + tg;
            uint32_t a0 = Xu[qr * 68 + c];
            uint32_t a1 = Xu[(qr + 8) * 68 + c];
            uint32_t a2 = Xu[qr * 68 + c + 4];
            uint32_t a3 = Xu[(qr + 8) * 68 + c + 4];
#pragma unroll
            for (int nt = 0; nt < 16; nt++) {
                int n0 = wc * 128 + nt * 8 + (lane >> 2);
                uint32_t b0 = Wu[n0 * 68 + c];
                uint32_t b1 = Wu[n0 * 68 + c + 4];
                mma_tf32(acc[nt], a0, a1, a2, a3, b0, b1);
            }
        }
        __syncthreads();
    }

    float ss0 = 0.f, ss1 = 0.f;
#pragma unroll
    for (int nt = 0; nt < 16; nt++) {
        ss0 += acc[nt][0] * acc[nt][0] + acc[nt][1] * acc[nt][1];
        ss1 += acc[nt][2] * acc[nt][2] + acc[nt][3] * acc[nt][3];
    }
#pragma unroll
    for (int o = 1; o < 4; o <<= 1) {
        ss0 += __shfl_xor_sync(0xffffffffu, ss0, o);
        ss1 += __shfl_xor_sync(0xffffffffu, ss1, o);
    }
    if (tg == 0) {
        ssPart[wc * 64 + qr] = ss0;
        ssPart[wc * 64 + qr + 8] = ss1;
    }
    __syncthreads();

    const float rad = radius[h];
    const float sc0 = rad / fmaxf(sqrtf(ssPart[qr] + ssPart[64 + qr]), 1e-12f);
    const float sc1 = rad / fmaxf(sqrtf(ssPart[qr + 8] + ssPart[64 + qr + 8]), 1e-12f);

    {
        const int gr0 = r0 + qr;
        const int b0i = gr0 >> 11, n0i = gr0 & 2047;
        const int gr1 = gr0 + 8;
        const int b1i = gr1 >> 11, n1i = gr1 & 2047;
        float* o0 = dst + ((size_t)(b0i * H + h) * N + n0i) * DQK;
        float* o1 = dst + ((size_t)(b1i * H + h) * N + n1i) * DQK;
#pragma unroll
        for (int nt = 0; nt < 16; nt++) {
            const int col = wc * 128 + nt * 8 + 2 * tg;
            *(float2*)(o0 + col) = make_float2(acc[nt][0] * sc0, acc[nt][1] * sc0);
            *(float2*)(o1 + col) = make_float2(acc[nt][2] * sc1, acc[nt][3] * sc1);
        }
    }
}

// ---------------------------------------------------------------------------
// Kernel 2: attention, sigma-in-smem.  CTA = 64 queries of (b,h); 64-key tiles.
// S phase: 4x2 warp grid (m16 x n32).  PV phase: 2x4 (m32 x n32).
// All smem operands sigma-interleaved -> every mma fragment load is LDS.64.
// Global layouts stay plain fp32 coalesced.  One-pass softmax, shift sqrt(128).
// ---------------------------------------------------------------------------
#define ATT_QO   0                      // 64 x 260 u32 = 66560 B
#define ATT_KO   66560                  // 64 x 260 u32
#define ATT_VO   133120                 // 128 x 68 u32 = 34816 B
#define ATT_PO   167936                 // 64 x 68 u32  = 17408 B
#define ATT_RSO  185344                 // 128 floats
#define ATT_INVO 185856                 // 64 floats
#define ATT_SMEM 186112

__global__ __launch_bounds__(256) void attn_mma_kernel()
{
    extern __shared__ char smem[];
    uint32_t* Qu = (uint32_t*)(smem + ATT_QO);
    uint32_t* Ku = (uint32_t*)(smem + ATT_KO);
    uint32_t* Vt = (uint32_t*)(smem + ATT_VO);
    uint32_t* Pu = (uint32_t*)(smem + ATT_PO);
    float* rsPart = (float*)(smem + ATT_RSO);
    float* invS   = (float*)(smem + ATT_INVO);

    const int nt_blk = blockIdx.x;
    const int h = blockIdx.y, b = blockIdx.z;
    const int tid = threadIdx.x;
    const int wid = tid >> 5, lane = tid & 31;
    const int rq = lane >> 2, tg = lane & 3;
    // S-phase mapping: 4 row groups (m16) x 2 col groups (n32)
    const int qrS = (wid & 3) * 16 + rq;
    const int wcS = wid >> 2;                 // 0..1
    // PV-phase mapping: 2 row groups (m32) x 4 col groups (n32)
    const int qrP = (wid & 1) * 32 + rq;
    const int wcP = wid >> 1;                 // 0..3

    const float* qbase = g_qn + ((size_t)(b * H + h) * N + nt_blk * 64) * DQK;
    const float* kbase = g_kn + ((size_t)(b * H + h) * M) * DQK;
    const uint32_t* vsrc = g_vt + (size_t)(b * H + h) * 32 * DV * 64;

    // Q tile -> smem (sigma, vectorized): thread handles one 8-col block
#pragma unroll
    for (int t = 0; t < 8; t++) {
        int i = tid + t * 256;
        int r = i >> 5, c8 = (i & 31) * 8;
        float4 v0 = *(const float4*)(qbase + (size_t)r * DQK + c8);
        float4 v1 = *(const float4*)(qbase + (size_t)r * DQK + c8 + 4);
        st_sigma8(Qu + r * 260 + c8, v0, v1);
    }

    float o_acc[4][2][4];
#pragma unroll
    for (int a = 0; a < 4; a++)
#pragma unroll
        for (int m2 = 0; m2 < 2; m2++)
#pragma unroll
            for (int j = 0; j < 4; j++) o_acc[a][m2][j] = 0.f;
    float rsum0 = 0.f, rsum1 = 0.f;

    const float SCALE = 0.08838834764831845f;  // 1/sqrt(128)
    const float SMAX  = 11.313708498984761f;   // sqrt(128)
    const int smap = (tg >> 1) + (tg & 1) * 4;

    for (int mt = 0; mt < M / 64; mt++) {
        // K tile 64 x 256 (sigma, vectorized)
        {
            const float* s = kbase + (size_t)mt * 64 * DQK;
#pragma unroll
            for (int t = 0; t < 8; t++) {
                int i = tid + t * 256;
                int r = i >> 5, c8 = (i & 31) * 8;
                float4 v0 = *(const float4*)(s + (size_t)r * DQK + c8);
                float4 v1 = *(const float4*)(s + (size_t)r * DQK + c8 + 4);
                st_sigma8(Ku + r * 260 + c8, v0, v1);
            }
        }
        // V^T tile 128 x 64 (already sigma in g_vt, plain uint4 copy)
        {
            const uint32_t* s = vsrc + (size_t)mt * DV * 64;
#pragma unroll
            for (int t = 0; t < 8; t++) {
                int i = tid + t * 256;
                int r = i >> 4, c4 = (i & 15) * 4;
                *(uint4*)(Vt + r * 68 + c4) = *(const uint4*)(s + (size_t)r * 64 + c4);
            }
        }
        __syncthreads();

        // ---- S = Q K^T (m16n32 per warp, k = 256) ----
        float s[4][4];
#pragma unroll
        for (int a = 0; a < 4; a++)
#pragma unroll
            for (int j = 0; j < 4; j++) s[a][j] = 0.f;
#pragma unroll 8
        for (int ks = 0; ks < 32; ks++) {
            const int ko = ks * 8 + 2 * tg;
            uint2 aA = *(const uint2*)(Qu + qrS * 260 + ko);
            uint2 aB = *(const uint2*)(Qu + (qrS + 8) * 260 + ko);
#pragma unroll
            for (int nt = 0; nt < 4; nt++) {
                uint2 bb = *(const uint2*)(Ku + (wcS * 32 + nt * 8 + rq) * 260 + ko);
                mma_tf32(s[nt], aA.x, aB.x, aA.y, aB.y, bb.x, bb.y);
            }
        }

        // ---- softmax epilogue -> P (tf32, sigma positions in smem) ----
#pragma unroll
        for (int nt = 0; nt < 4; nt++) {
            float p0 = __expf(fmaf(s[nt][0], SCALE, -SMAX));
            float p1 = __expf(fmaf(s[nt][1], SCALE, -SMAX));
            float p2 = __expf(fmaf(s[nt][2], SCALE, -SMAX));
            float p3 = __expf(fmaf(s[nt][3], SCALE, -SMAX));
            rsum0 += p0 + p1;
            rsum1 += p2 + p3;
            const int pos = wcS * 32 + nt * 8 + smap;
            Pu[qrS * 68 + pos]           = f2tf32(p0);
            Pu[qrS * 68 + pos + 2]       = f2tf32(p1);
            Pu[(qrS + 8) * 68 + pos]     = f2tf32(p2);
            Pu[(qrS + 8) * 68 + pos + 2] = f2tf32(p3);
        }
        __syncthreads();

        // ---- O += P V (m32n32 per warp, k = 64) ----
#pragma unroll
        for (int ks = 0; ks < 8; ks++) {
            const int ko = ks * 8 + 2 * tg;
            uint2 pA = *(const uint2*)(Pu + qrP * 68 + ko);
            uint2 pB = *(const uint2*)(Pu + (qrP + 8) * 68 + ko);
            uint2 pC = *(const uint2*)(Pu + (qrP + 16) * 68 + ko);
            uint2 pD = *(const uint2*)(Pu + (qrP + 24) * 68 + ko);
#pragma unroll
            for (int nt = 0; nt < 4; nt++) {
                uint2 vv = *(const uint2*)(Vt + (wcP * 32 + nt * 8 + rq) * 68 + ko);
                mma_tf32(o_acc[nt][0], pA.x, pB.x, pA.y, pB.y, vv.x, vv.y);
                mma_tf32(o_acc[nt][1], pC.x, pD.x, pC.y, pD.y, vv.x, vv.y);
            }
        }
        __syncthreads();
    }

    // ---- row sums -> 1/sum ----
#pragma unroll
    for (int o = 1; o < 4; o <<= 1) {
        rsum0 += __shfl_xor_sync(0xffffffffu, rsum0, o);
        rsum1 += __shfl_xor_sync(0xffffffffu, rsum1, o);
    }
    if (tg == 0) {
        rsPart[wcS * 64 + qrS] = rsum0;
        rsPart[wcS * 64 + qrS + 8] = rsum1;
    }
    __syncthreads();
    if (tid < 64) invS[tid] = 1.f / (rsPart[tid] + rsPart[64 + tid]);
    __syncthreads();

    // ---- write O (plain fp32, coalesced float2) ----
    const float i0 = invS[qrP], i1 = invS[qrP + 8], i2 = invS[qrP + 16], i3 = invS[qrP + 24];
    float* o0 = g_o + ((size_t)(b * N + nt_blk * 64 + qrP)) * C + h * DV;
    float* o1 = o0 + (size_t)8 * C;
    float* o2 = o0 + (size_t)16 * C;
    float* o3 = o0 + (size_t)24 * C;
#pragma unroll
    for (int nt = 0; nt < 4; nt++) {
        const int col = wcP * 32 + nt * 8 + 2 * tg;
        *(float2*)(o0 + col) = make_float2(o_acc[nt][0][0] * i0, o_acc[nt][0][1] * i0);
        *(float2*)(o1 + col) = make_float2(o_acc[nt][0][2] * i1, o_acc[nt][0][3] * i1);
        *(float2*)(o2 + col) = make_float2(o_acc[nt][1][0] * i2, o_acc[nt][1][1] * i2);
        *(float2*)(o3 + col) = make_float2(o_acc[nt][1][2] * i3, o_acc[nt][1][3] * i3);
    }
}

// ---------------------------------------------------------------------------
// Kernel 3: output projection, tf32 mma (unchanged from R10 — verified)
// ---------------------------------------------------------------------------
__global__ __launch_bounds__(256) void proj_tc_kernel(
    const float* __restrict__ Wproj, float* __restrict__ out)
{
    extern __shared__ float sm[];
    uint32_t* Xu = (uint32_t*)(sm + QKV_XS);
    uint32_t* Wu = (uint32_t*)(sm + QKV_WS);

    const int r0 = blockIdx.x * 64;
    const int c0 = blockIdx.y * 256;
    const int tid = threadIdx.x;
    const int wid = tid >> 5;
    const int lane = tid & 31;
    const int wr = wid & 3;
    const int wc = wid >> 2;
    const int qr = wr * 16 + (lane >> 2);
    const int tg = lane & 3;

    float acc[16][4];
#pragma unroll
    for (int i = 0; i < 16; i++)
#pragma unroll
        for (int j = 0; j < 4; j++) acc[i][j] = 0.f;

    for (int kc = 0; kc < 8; kc++) {
#pragma unroll
        for (int t = 0; t < 4; t++) {
            int i = tid + t * 256;
            int r = i >> 4, cc = (i & 15) * 4;
            float4 v = *(const float4*)(g_o + (size_t)(r0 + r) * C + kc * 64 + cc);
            *(uint4*)(Xu + r * 68 + cc) = cvt4(v);
        }
#pragma unroll
        for (int t = 0; t < 16; t++) {
            int i = tid + t * 256;
            int r = i >> 4, cc = (i & 15) * 4;
            float4 v = *(const float4*)(Wproj + (size_t)(c0 + r) * C + kc * 64 + cc);
            *(uint4*)(Wu + r * 68 + cc) = cvt4(v);
        }
        __syncthreads();

#pragma unroll
        for (int ks = 0; ks < 8; ks++) {
            const int c = ks * 8 + tg;
            uint32_t a0 = Xu[qr * 68 + c];
            uint32_t a1 = Xu[(qr + 8) * 68 + c];
            uint32_t a2 = Xu[qr * 68 + c + 4];
            uint32_t a3 = Xu[(qr + 8) * 68 + c + 4];
#pragma unroll
            for (int nt = 0; nt < 16; nt++) {
                int n0 = wc * 128 + nt * 8 + (lane >> 2);
                uint32_t b0 = Wu[n0 * 68 + c];
                uint32_t b1 = Wu[n0 * 68 + c + 4];
                mma_tf32(acc[nt], a0, a1, a2, a3, b0, b1);
            }
        }
        __syncthreads();
    }

    {
        float* o0 = out + (size_t)(r0 + qr) * C + c0;
        float* o1 = out + (size_t)(r0 + qr + 8) * C + c0;
#pragma unroll
        for (int nt = 0; nt < 16; nt++) {
            const int col = wc * 128 + nt * 8 + 2 * tg;
            *(float2*)(o0 + col) = make_float2(acc[nt][0], acc[nt][1]);
            *(float2*)(o1 + col) = make_float2(acc[nt][2], acc[nt][3]);
        }
    }
}

// ---------------------------------------------------------------------------
extern "C" void kernel_launch(void* const* d_in, const int* in_sizes, int n_in,
                              void* d_out, int out_size)
{
    const float* x      = (const float*)d_in[0];
    const float* ctx    = (const float*)d_in[1];
    const float* Wqkv   = (const float*)d_in[2];
    const float* Wproj  = (const float*)d_in[3];
    const float* radius = (const float*)d_in[4];
    float* out = (float*)d_out;

    (void)in_sizes; (void)n_in; (void)out_size;

    cudaFuncSetAttribute(qkv_mma_kernel,
                         cudaFuncAttributeMaxDynamicSharedMemorySize, QKV_SMEM);
    cudaFuncSetAttribute(attn_mma_kernel,
                         cudaFuncAttributeMaxDynamicSharedMemorySize, ATT_SMEM);
    cudaFuncSetAttribute(proj_tc_kernel,
                         cudaFuncAttributeMaxDynamicSharedMemorySize, QKV_SMEM);

    // pre-pass: arrange V^T tiles (tf32 sigma) — verified in R6
    v_arrange_kernel<<<B * M, 128>>>(ctx);

    // 1) QKV projection + per-head L2 norm (x -> g_qn, context -> g_kn)
    qkv_mma_kernel<<<dim3((B * N) / 64, H, 2), 256, QKV_SMEM>>>(x, ctx, Wqkv, radius);

    // 2) attention per (b,h), 64-query tiles, sigma-in-smem tf32 mma
    attn_mma_kernel<<<dim3(N / 64, H, B), 256, ATT_SMEM>>>();

    // 3) output projection (tf32 mma)
    proj_tc_kernel<<<dim3((B * N) / 64, C / 256), 256, QKV_SMEM>>>(Wproj, out);
}

// round 13
// speedup vs baseline: 1.6073x; 1.6073x over previous
#include <cuda_runtime.h>
#include <math.h>
#include <stdint.h>

#define B 4
#define N 2048
#define M 2048
#define C 512
#define H 4
#define DV 128
#define DQK 256

// scratch: tf32-bits payloads in PLAIN coalesced layouts
__device__ __align__(16) uint32_t g_qn[B * H * N * DQK];   // normed Q (tf32 bits)
__device__ __align__(16) uint32_t g_kn[B * H * M * DQK];   // normed K (tf32 bits)
__device__ __align__(16) uint32_t g_vc[B * M * C];         // ctx (tf32 bits)
__device__ __align__(16) float    g_o [B * N * C];         // attn out fp32

// ============================================================================
// helpers
// ============================================================================
__device__ __forceinline__ uint32_t f2tf32(float f) {
    uint32_t u;
    asm("cvt.rna.tf32.f32 %0, %1;" : "=r"(u) : "f"(f));
    return u;
}
__device__ __forceinline__ uint4 cvt4(float4 v) {
    uint4 u;
    u.x = f2tf32(v.x); u.y = f2tf32(v.y); u.z = f2tf32(v.z); u.w = f2tf32(v.w);
    return u;
}
__device__ __forceinline__ void mma_tf32(float* c,
                                         uint32_t a0, uint32_t a1, uint32_t a2, uint32_t a3,
                                         uint32_t b0, uint32_t b1) {
    asm volatile(
        "mma.sync.aligned.m16n8k8.row.col.f32.tf32.tf32.f32 "
        "{%0,%1,%2,%3}, {%4,%5,%6,%7}, {%8,%9}, {%0,%1,%2,%3};"
        : "+f"(c[0]), "+f"(c[1]), "+f"(c[2]), "+f"(c[3])
        : "r"(a0), "r"(a1), "r"(a2), "r"(a3), "r"(b0), "r"(b1));
}
__device__ __forceinline__ uint32_t smem_u32(const void* p) {
    uint32_t a;
    asm("{ .reg .u64 t; cvta.to.shared.u64 t, %1; cvt.u32.u64 %0, t; }" : "=r"(a) : "l"(p));
    return a;
}
#define CPA(d, s) asm volatile("cp.async.ca.shared.global [%0], [%1], 16;" :: "r"(d), "l"(s))
#define CP_COMMIT() asm volatile("cp.async.commit_group;" ::: "memory")
#define CP_WAIT0()  asm volatile("cp.async.wait_group 0;" ::: "memory")

// ---------------------------------------------------------------------------
// Pre-pass: ctx fp32 -> g_vc tf32 bits (plain layout, coalesced)
// ---------------------------------------------------------------------------
__global__ __launch_bounds__(256) void ctx_cvt_kernel(const float* __restrict__ ctx)
{
    const size_t idx = (size_t)(blockIdx.x * 256 + threadIdx.x) * 4;
    float4 v = *(const float4*)(ctx + idx);
    *(uint4*)(g_vc + idx) = cvt4(v);
}

// ---------------------------------------------------------------------------
// Kernel 1: fused QKV projection + per-head L2 norm * radius, tf32 mma.
// (R10-exact except outputs stored as tf32 bits)
// ---------------------------------------------------------------------------
#define QKV_XS   0                    // 64 x 68 u32
#define QKV_WS   (64 * 68)            // 256 x 68 u32
#define QKV_SS   (QKV_WS + 256 * 68)  // 2 x 64 floats
#define QKV_SMEM ((QKV_SS + 128) * 4)

__global__ __launch_bounds__(256) void qkv_mma_kernel(
    const float* __restrict__ x, const float* __restrict__ ctx,
    const float* __restrict__ Wqkv, const float* __restrict__ radius)
{
    extern __shared__ float sm[];
    uint32_t* Xu = (uint32_t*)(sm + QKV_XS);
    uint32_t* Wu = (uint32_t*)(sm + QKV_WS);
    float* ssPart = sm + QKV_SS;

    const float* src = (blockIdx.z == 0) ? x : ctx;
    uint32_t* dst = (blockIdx.z == 0) ? g_qn : g_kn;
    const int h  = blockIdx.y;
    const int r0 = blockIdx.x * 64;
    const int tid = threadIdx.x;
    const int wid = tid >> 5;
    const int lane = tid & 31;
    const int wr = wid & 3;
    const int wc = wid >> 2;
    const int qr = wr * 16 + (lane >> 2);
    const int tg = lane & 3;

    float acc[16][4];
#pragma unroll
    for (int i = 0; i < 16; i++)
#pragma unroll
        for (int j = 0; j < 4; j++) acc[i][j] = 0.f;

    for (int kc = 0; kc < 8; kc++) {
#pragma unroll
        for (int t = 0; t < 4; t++) {
            int i = tid + t * 256;
            int r = i >> 4, cc = (i & 15) * 4;
            float4 v = *(const float4*)(src + (size_t)(r0 + r) * C + kc * 64 + cc);
            *(uint4*)(Xu + r * 68 + cc) = cvt4(v);
        }
#pragma unroll
        for (int t = 0; t < 16; t++) {
            int i = tid + t * 256;
            int r = i >> 4, cc = (i & 15) * 4;
            float4 v = *(const float4*)(Wqkv + (size_t)(h * 256 + r) * C + kc * 64 + cc);
            *(uint4*)(Wu + r * 68 + cc) = cvt4(v);
        }
        __syncthreads();

#pragma unroll
        for (int ks = 0; ks < 8; ks++) {
            const int c = ks * 8 + tg;
            uint32_t a0 = Xu[qr * 68 + c];
            uint32_t a1 = Xu[(qr + 8) * 68 + c];
            uint32_t a2 = Xu[qr * 68 + c + 4];
            uint32_t a3 = Xu[(qr + 8) * 68 + c + 4];
#pragma unroll
            for (int nt = 0; nt < 16; nt++) {
                int n0 = wc * 128 + nt * 8 + (lane >> 2);
                uint32_t b0 = Wu[n0 * 68 + c];
                uint32_t b1 = Wu[n0 * 68 + c + 4];
                mma_tf32(acc[nt], a0, a1, a2, a3, b0, b1);
            }
        }
        __syncthreads();
    }

    float ss0 = 0.f, ss1 = 0.f;
#pragma unroll
    for (int nt = 0; nt < 16; nt++) {
        ss0 += acc[nt][0] * acc[nt][0] + acc[nt][1] * acc[nt][1];
        ss1 += acc[nt][2] * acc[nt][2] + acc[nt][3] * acc[nt][3];
    }
#pragma unroll
    for (int o = 1; o < 4; o <<= 1) {
        ss0 += __shfl_xor_sync(0xffffffffu, ss0, o);
        ss1 += __shfl_xor_sync(0xffffffffu, ss1, o);
    }
    if (tg == 0) {
        ssPart[wc * 64 + qr] = ss0;
        ssPart[wc * 64 + qr + 8] = ss1;
    }
    __syncthreads();

    const float rad = radius[h];
    const float sc0 = rad / fmaxf(sqrtf(ssPart[qr] + ssPart[64 + qr]), 1e-12f);
    const float sc1 = rad / fmaxf(sqrtf(ssPart[qr + 8] + ssPart[64 + qr + 8]), 1e-12f);

    {
        const int gr0 = r0 + qr;
        const int b0i = gr0 >> 11, n0i = gr0 & 2047;
        const int gr1 = gr0 + 8;
        const int b1i = gr1 >> 11, n1i = gr1 & 2047;
        uint32_t* o0 = dst + ((size_t)(b0i * H + h) * N + n0i) * DQK;
        uint32_t* o1 = dst + ((size_t)(b1i * H + h) * N + n1i) * DQK;
#pragma unroll
        for (int nt = 0; nt < 16; nt++) {
            const int col = wc * 128 + nt * 8 + 2 * tg;
            *(uint2*)(o0 + col) = make_uint2(f2tf32(acc[nt][0] * sc0), f2tf32(acc[nt][1] * sc0));
            *(uint2*)(o1 + col) = make_uint2(f2tf32(acc[nt][2] * sc1), f2tf32(acc[nt][3] * sc1));
        }
    }
}

// ---------------------------------------------------------------------------
// Kernel 2: attention (R10 fragment code) + cp.async overlapped loads.
// CTA = 64 queries of one (b,h); 64-key tiles, 32 iters.
// V double-buffered; K prefetched after S-phase (overlaps PV).
// ---------------------------------------------------------------------------
#define ATT_QO   0                      // 64 x 260 u32 = 66560 B
#define ATT_KO   66560                  // 64 x 260 u32 = 66560 B
#define ATT_VO   133120                 // 2 x (64 x 136 u32 = 34816 B)
#define ATT_PO   202752                 // 64 x 68 u32 = 17408 B
#define ATT_RSO  220160                 // 128 floats = 512 B
#define ATT_SMEM 220672

__global__ __launch_bounds__(256) void attn_mma_kernel()
{
    extern __shared__ char smem[];
    const uint32_t sbase = smem_u32(smem);
    uint32_t* Qu = (uint32_t*)(smem + ATT_QO);
    uint32_t* Ku = (uint32_t*)(smem + ATT_KO);
    uint32_t* Pu = (uint32_t*)(smem + ATT_PO);
    float* rsPart = (float*)(smem + ATT_RSO);

    const int nt_blk = blockIdx.x;
    const int h  = blockIdx.y;
    const int b  = blockIdx.z;
    const int tid = threadIdx.x;
    const int wid = tid >> 5;
    const int lane = tid & 31;
    const int wr = wid & 3;
    const int wc = wid >> 2;
    const int qr = wr * 16 + (lane >> 2);
    const int tg = lane & 3;

    const uint32_t* qsrc = g_qn + ((size_t)(b * H + h) * N + nt_blk * 64) * DQK;
    const uint32_t* ksrc = g_kn + ((size_t)(b * H + h) * M) * DQK;
    const uint32_t* vsrc = g_vc + (size_t)b * M * C + h * DV;

    auto issue_k = [&](int mt) {
        const uint32_t kd = sbase + ATT_KO;
        const uint32_t* s = ksrc + (size_t)mt * 64 * DQK;
#pragma unroll
        for (int t = 0; t < 16; t++) {
            int i = tid + t * 256;
            int r = i >> 6, c = i & 63;                      // 64 rows x 64 chunks
            CPA(kd + (uint32_t)(r * 1040 + c * 16), s + (size_t)r * DQK + c * 4);
        }
        CP_COMMIT();
    };
    auto issue_v = [&](int mt, int bi) {
        const uint32_t vd = sbase + ATT_VO + bi * 34816;
        const uint32_t* s = vsrc + (size_t)(mt * 64) * C;
#pragma unroll
        for (int t = 0; t < 8; t++) {
            int i = tid + t * 256;
            int r = i >> 5, c = i & 31;                      // 64 rows x 32 chunks
            CPA(vd + (uint32_t)(r * 544 + c * 16), s + (size_t)r * C + c * 4);
        }
        CP_COMMIT();
    };

    // prologue: Q + K0 + V0
    {
        const uint32_t qd = sbase + ATT_QO;
#pragma unroll
        for (int t = 0; t < 16; t++) {
            int i = tid + t * 256;
            int r = i >> 6, c = i & 63;
            CPA(qd + (uint32_t)(r * 1040 + c * 16), qsrc + (size_t)r * DQK + c * 4);
        }
        CP_COMMIT();
    }
    issue_k(0);
    issue_v(0, 0);
    CP_WAIT0();
    __syncthreads();

    float o_acc[8][4];
#pragma unroll
    for (int i = 0; i < 8; i++)
#pragma unroll
        for (int j = 0; j < 4; j++) o_acc[i][j] = 0.f;
    float rsum0 = 0.f, rsum1 = 0.f;

    const float SCALE = 0.08838834764831845f;  // 1/sqrt(128)
    const float SMAX  = 11.313708498984761f;   // sqrt(128)

    for (int mt = 0; mt < M / 64; mt++) {
        const int cur = mt & 1;
        if (mt + 1 < M / 64) issue_v(mt + 1, cur ^ 1);   // overlaps S-phase

        // ---- S = Q K^T : warp tile 16 rows x 32 cols, k = 256 ----
        float s[4][4];
#pragma unroll
        for (int i = 0; i < 4; i++)
#pragma unroll
            for (int j = 0; j < 4; j++) s[i][j] = 0.f;
#pragma unroll
        for (int ks = 0; ks < 32; ks++) {
            const int c = ks * 8 + tg;
            uint32_t a0 = Qu[qr * 260 + c];
            uint32_t a1 = Qu[(qr + 8) * 260 + c];
            uint32_t a2 = Qu[qr * 260 + c + 4];
            uint32_t a3 = Qu[(qr + 8) * 260 + c + 4];
#pragma unroll
            for (int nt = 0; nt < 4; nt++) {
                int n0 = wc * 32 + nt * 8 + (lane >> 2);
                uint32_t b0 = Ku[n0 * 260 + c];
                uint32_t b1 = Ku[n0 * 260 + c + 4];
                mma_tf32(s[nt], a0, a1, a2, a3, b0, b1);
            }
        }

        // ---- softmax epilogue -> P (tf32) in smem ----
#pragma unroll
        for (int nt = 0; nt < 4; nt++) {
            float p0 = __expf(fmaf(s[nt][0], SCALE, -SMAX));
            float p1 = __expf(fmaf(s[nt][1], SCALE, -SMAX));
            float p2 = __expf(fmaf(s[nt][2], SCALE, -SMAX));
            float p3 = __expf(fmaf(s[nt][3], SCALE, -SMAX));
            rsum0 += p0 + p1;
            rsum1 += p2 + p3;
            const int col = wc * 32 + nt * 8 + 2 * tg;
            *(uint2*)(Pu + qr * 68 + col) = make_uint2(f2tf32(p0), f2tf32(p1));
            *(uint2*)(Pu + (qr + 8) * 68 + col) = make_uint2(f2tf32(p2), f2tf32(p3));
        }
        __syncthreads();                          // K free, P visible

        if (mt + 1 < M / 64) issue_k(mt + 1);     // overlaps PV

        // ---- O += P V : warp tile 16 rows x 64 cols, k = 64 ----
        const uint32_t* Vu = (const uint32_t*)(smem + ATT_VO + cur * 34816);
#pragma unroll
        for (int ks = 0; ks < 8; ks++) {
            const int c = ks * 8 + tg;
            uint32_t a0 = Pu[qr * 68 + c];
            uint32_t a1 = Pu[(qr + 8) * 68 + c];
            uint32_t a2 = Pu[qr * 68 + c + 4];
            uint32_t a3 = Pu[(qr + 8) * 68 + c + 4];
#pragma unroll
            for (int nt = 0; nt < 8; nt++) {
                int n0 = wc * 64 + nt * 8 + (lane >> 2);
                uint32_t b0 = Vu[c * 136 + n0];
                uint32_t b1 = Vu[(c + 4) * 136 + n0];
                mma_tf32(o_acc[nt], a0, a1, a2, a3, b0, b1);
            }
        }
        CP_WAIT0();
        __syncthreads();
    }

    // ---- row-sum reduction: quad, then across the two wc halves ----
#pragma unroll
    for (int o = 1; o < 4; o <<= 1) {
        rsum0 += __shfl_xor_sync(0xffffffffu, rsum0, o);
        rsum1 += __shfl_xor_sync(0xffffffffu, rsum1, o);
    }
    if (tg == 0) {
        rsPart[wc * 64 + qr] = rsum0;
        rsPart[wc * 64 + qr + 8] = rsum1;
    }
    __syncthreads();
    const float inv0 = 1.f / (rsPart[qr] + rsPart[64 + qr]);
    const float inv1 = 1.f / (rsPart[qr + 8] + rsPart[64 + qr + 8]);

    // ---- write O (fp32, coalesced float2) ----
    {
        const int n0g = nt_blk * 64 + qr;
        float* o0 = g_o + ((size_t)(b * N + n0g)) * C + h * DV;
        float* o1 = g_o + ((size_t)(b * N + n0g + 8)) * C + h * DV;
#pragma unroll
        for (int nt = 0; nt < 8; nt++) {
            const int col = wc * 64 + nt * 8 + 2 * tg;
            *(float2*)(o0 + col) = make_float2(o_acc[nt][0] * inv0, o_acc[nt][1] * inv0);
            *(float2*)(o1 + col) = make_float2(o_acc[nt][2] * inv1, o_acc[nt][3] * inv1);
        }
    }
}

// ---------------------------------------------------------------------------
// Kernel 3: output projection, tf32 mma (R10-exact)
// ---------------------------------------------------------------------------
__global__ __launch_bounds__(256) void proj_tc_kernel(
    const float* __restrict__ Wproj, float* __restrict__ out)
{
    extern __shared__ float sm[];
    uint32_t* Xu = (uint32_t*)(sm + QKV_XS);
    uint32_t* Wu = (uint32_t*)(sm + QKV_WS);

    const int r0 = blockIdx.x * 64;
    const int c0 = blockIdx.y * 256;
    const int tid = threadIdx.x;
    const int wid = tid >> 5;
    const int lane = tid & 31;
    const int wr = wid & 3;
    const int wc = wid >> 2;
    const int qr = wr * 16 + (lane >> 2);
    const int tg = lane & 3;

    float acc[16][4];
#pragma unroll
    for (int i = 0; i < 16; i++)
#pragma unroll
        for (int j = 0; j < 4; j++) acc[i][j] = 0.f;

    for (int kc = 0; kc < 8; kc++) {
#pragma unroll
        for (int t = 0; t < 4; t++) {
            int i = tid + t * 256;
            int r = i >> 4, cc = (i & 15) * 4;
            float4 v = *(const float4*)(g_o + (size_t)(r0 + r) * C + kc * 64 + cc);
            *(uint4*)(Xu + r * 68 + cc) = cvt4(v);
        }
#pragma unroll
        for (int t = 0; t < 16; t++) {
            int i = tid + t * 256;
            int r = i >> 4, cc = (i & 15) * 4;
            float4 v = *(const float4*)(Wproj + (size_t)(c0 + r) * C + kc * 64 + cc);
            *(uint4*)(Wu + r * 68 + cc) = cvt4(v);
        }
        __syncthreads();

#pragma unroll
        for (int ks = 0; ks < 8; ks++) {
            const int c = ks * 8 + tg;
            uint32_t a0 = Xu[qr * 68 + c];
            uint32_t a1 = Xu[(qr + 8) * 68 + c];
            uint32_t a2 = Xu[qr * 68 + c + 4];
            uint32_t a3 = Xu[(qr + 8) * 68 + c + 4];
#pragma unroll
            for (int nt = 0; nt < 16; nt++) {
                int n0 = wc * 128 + nt * 8 + (lane >> 2);
                uint32_t b0 = Wu[n0 * 68 + c];
                uint32_t b1 = Wu[n0 * 68 + c + 4];
                mma_tf32(acc[nt], a0, a1, a2, a3, b0, b1);
            }
        }
        __syncthreads();
    }

    {
        float* o0 = out + (size_t)(r0 + qr) * C + c0;
        float* o1 = out + (size_t)(r0 + qr + 8) * C + c0;
#pragma unroll
        for (int nt = 0; nt < 16; nt++) {
            const int col = wc * 128 + nt * 8 + 2 * tg;
            *(float2*)(o0 + col) = make_float2(acc[nt][0], acc[nt][1]);
            *(float2*)(o1 + col) = make_float2(acc[nt][2], acc[nt][3]);
        }
    }
}

// ---------------------------------------------------------------------------
extern "C" void kernel_launch(void* const* d_in, const int* in_sizes, int n_in,
                              void* d_out, int out_size)
{
    const float* x      = (const float*)d_in[0];
    const float* ctx    = (const float*)d_in[1];
    const float* Wqkv   = (const float*)d_in[2];
    const float* Wproj  = (const float*)d_in[3];
    const float* radius = (const float*)d_in[4];
    float* out = (float*)d_out;

    (void)in_sizes; (void)n_in; (void)out_size;

    cudaFuncSetAttribute(qkv_mma_kernel,
                         cudaFuncAttributeMaxDynamicSharedMemorySize, QKV_SMEM);
    cudaFuncSetAttribute(attn_mma_kernel,
                         cudaFuncAttributeMaxDynamicSharedMemorySize, ATT_SMEM);
    cudaFuncSetAttribute(proj_tc_kernel,
                         cudaFuncAttributeMaxDynamicSharedMemorySize, QKV_SMEM);

    // pre-pass: ctx -> tf32 bits (for cp.async V loads)
    ctx_cvt_kernel<<<(B * M * C / 4) / 256, 256>>>(ctx);

    // 1) QKV projection + per-head L2 norm (tf32-bit outputs)
    qkv_mma_kernel<<<dim3((B * N) / 64, H, 2), 256, QKV_SMEM>>>(x, ctx, Wqkv, radius);

    // 2) attention per (b,h), 64-query tiles, cp.async overlapped
    attn_mma_kernel<<<dim3(N / 64, H, B), 256, ATT_SMEM>>>();

    // 3) output projection (tf32 mma)
    proj_tc_kernel<<<dim3((B * N) / 64, C / 256), 256, QKV_SMEM>>>(Wproj, out);
}

// round 14
// speedup vs baseline: 1.7327x; 1.0780x over previous
#include <cuda_runtime.h>
#include <math.h>
#include <stdint.h>

#define B 4
#define N 2048
#define M 2048
#define C 512
#define H 4
#define DV 128
#define DQK 256

// scratch: tf32-bits payloads in PLAIN coalesced layouts
__device__ __align__(16) uint32_t g_xs[B * N * C];         // x (tf32 bits)
__device__ __align__(16) uint32_t g_vc[B * M * C];         // ctx (tf32 bits)
__device__ __align__(16) uint32_t g_wq[2 * C * C];         // Wqkv (tf32 bits)
__device__ __align__(16) uint32_t g_wp[C * C];             // Wproj (tf32 bits)
__device__ __align__(16) uint32_t g_qn[B * H * N * DQK];   // normed Q (tf32 bits)
__device__ __align__(16) uint32_t g_kn[B * H * M * DQK];   // normed K (tf32 bits)
__device__ __align__(16) uint32_t g_o [B * N * C];         // attn out (tf32 bits)

// ============================================================================
// helpers
// ============================================================================
__device__ __forceinline__ uint32_t f2tf32(float f) {
    uint32_t u;
    asm("cvt.rna.tf32.f32 %0, %1;" : "=r"(u) : "f"(f));
    return u;
}
__device__ __forceinline__ uint4 cvt4(float4 v) {
    uint4 u;
    u.x = f2tf32(v.x); u.y = f2tf32(v.y); u.z = f2tf32(v.z); u.w = f2tf32(v.w);
    return u;
}
__device__ __forceinline__ void mma_tf32(float* c,
                                         uint32_t a0, uint32_t a1, uint32_t a2, uint32_t a3,
                                         uint32_t b0, uint32_t b1) {
    asm volatile(
        "mma.sync.aligned.m16n8k8.row.col.f32.tf32.tf32.f32 "
        "{%0,%1,%2,%3}, {%4,%5,%6,%7}, {%8,%9}, {%0,%1,%2,%3};"
        : "+f"(c[0]), "+f"(c[1]), "+f"(c[2]), "+f"(c[3])
        : "r"(a0), "r"(a1), "r"(a2), "r"(a3), "r"(b0), "r"(b1));
}
__device__ __forceinline__ uint32_t smem_u32(const void* p) {
    uint32_t a;
    asm("{ .reg .u64 t; cvta.to.shared.u64 t, %1; cvt.u32.u64 %0, t; }" : "=r"(a) : "l"(p));
    return a;
}
#define CPA(d, s) asm volatile("cp.async.ca.shared.global [%0], [%1], 16;" :: "r"(d), "l"(s))
#define CP_COMMIT() asm volatile("cp.async.commit_group;" ::: "memory")
#define CP_WAIT0()  asm volatile("cp.async.wait_group 0;" ::: "memory")
#define CP_WAIT1()  asm volatile("cp.async.wait_group 1;" ::: "memory")

// ---------------------------------------------------------------------------
// Pre-pass: fp32 -> tf32 bits (plain layout, coalesced)
// ---------------------------------------------------------------------------
__global__ __launch_bounds__(256) void cvt_kernel(
    const float* __restrict__ src, uint32_t* __restrict__ dst)
{
    const size_t idx = (size_t)(blockIdx.x * 256 + threadIdx.x) * 4;
    float4 v = *(const float4*)(src + idx);
    *(uint4*)(dst + idx) = cvt4(v);
}

// ---------------------------------------------------------------------------
// Kernel 1: fused QKV projection + per-head L2 norm * radius, tf32 mma.
// R10 fragment code; cp.async double-buffered X/W chunks from tf32 globals.
// CTA = 64 rows x 256 cols (one head), k = 512 in 8 chunks.
// ---------------------------------------------------------------------------
#define QKV_XB(i)  ((i) * 17408)             // 2 x (64 x 68 u32)
#define QKV_WB(i)  (34816 + (i) * 69632)     // 2 x (256 x 68 u32)
#define QKV_SS     174080                    // 2 x 64 floats
#define QKV_SMEM   174592

__global__ __launch_bounds__(256) void qkv_mma_kernel(const float* __restrict__ radius)
{
    extern __shared__ char smem[];
    const uint32_t sbase = smem_u32(smem);
    float* ssPart = (float*)(smem + QKV_SS);

    const uint32_t* Asrc = (blockIdx.z == 0) ? g_xs : g_vc;
    uint32_t* dst = (blockIdx.z == 0) ? g_qn : g_kn;
    const int h  = blockIdx.y;
    const int r0 = blockIdx.x * 64;
    const int tid = threadIdx.x;
    const int wid = tid >> 5;
    const int lane = tid & 31;
    const int wr = wid & 3;
    const int wc = wid >> 2;
    const int qr = wr * 16 + (lane >> 2);
    const int tg = lane & 3;

    const uint32_t* abase = Asrc + (size_t)r0 * C;
    const uint32_t* wbase = g_wq + (size_t)(h * 256) * C;

    auto issue = [&](int kc, int bi) {
        const uint32_t xd = sbase + QKV_XB(bi);
        const uint32_t wd = sbase + QKV_WB(bi);
#pragma unroll
        for (int t = 0; t < 4; t++) {
            int i = tid + t * 256;
            int r = i >> 4, c = i & 15;                 // 64 rows x 16 chunks
            CPA(xd + (uint32_t)(r * 272 + c * 16), abase + (size_t)r * C + kc * 64 + c * 4);
        }
#pragma unroll
        for (int t = 0; t < 16; t++) {
            int i = tid + t * 256;
            int r = i >> 4, c = i & 15;                 // 256 rows x 16 chunks
            CPA(wd + (uint32_t)(r * 272 + c * 16), wbase + (size_t)r * C + kc * 64 + c * 4);
        }
        CP_COMMIT();
    };

    float acc[16][4];
#pragma unroll
    for (int i = 0; i < 16; i++)
#pragma unroll
        for (int j = 0; j < 4; j++) acc[i][j] = 0.f;

    issue(0, 0);
    for (int kc = 0; kc < 8; kc++) {
        if (kc < 7) issue(kc + 1, (kc + 1) & 1);
        if (kc < 7) { CP_WAIT1(); } else { CP_WAIT0(); }
        __syncthreads();
        const uint32_t* Xu = (const uint32_t*)(smem + QKV_XB(kc & 1));
        const uint32_t* Wu = (const uint32_t*)(smem + QKV_WB(kc & 1));
#pragma unroll
        for (int ks = 0; ks < 8; ks++) {
            const int c = ks * 8 + tg;
            uint32_t a0 = Xu[qr * 68 + c];
            uint32_t a1 = Xu[(qr + 8) * 68 + c];
            uint32_t a2 = Xu[qr * 68 + c + 4];
            uint32_t a3 = Xu[(qr + 8) * 68 + c + 4];
#pragma unroll
            for (int nt = 0; nt < 16; nt++) {
                int n0 = wc * 128 + nt * 8 + (lane >> 2);
                uint32_t b0 = Wu[n0 * 68 + c];
                uint32_t b1 = Wu[n0 * 68 + c + 4];
                mma_tf32(acc[nt], a0, a1, a2, a3, b0, b1);
            }
        }
        __syncthreads();
    }

    float ss0 = 0.f, ss1 = 0.f;
#pragma unroll
    for (int nt = 0; nt < 16; nt++) {
        ss0 += acc[nt][0] * acc[nt][0] + acc[nt][1] * acc[nt][1];
        ss1 += acc[nt][2] * acc[nt][2] + acc[nt][3] * acc[nt][3];
    }
#pragma unroll
    for (int o = 1; o < 4; o <<= 1) {
        ss0 += __shfl_xor_sync(0xffffffffu, ss0, o);
        ss1 += __shfl_xor_sync(0xffffffffu, ss1, o);
    }
    if (tg == 0) {
        ssPart[wc * 64 + qr] = ss0;
        ssPart[wc * 64 + qr + 8] = ss1;
    }
    __syncthreads();

    const float rad = radius[h];
    const float sc0 = rad / fmaxf(sqrtf(ssPart[qr] + ssPart[64 + qr]), 1e-12f);
    const float sc1 = rad / fmaxf(sqrtf(ssPart[qr + 8] + ssPart[64 + qr + 8]), 1e-12f);

    {
        const int gr0 = r0 + qr;
        const int b0i = gr0 >> 11, n0i = gr0 & 2047;
        const int gr1 = gr0 + 8;
        const int b1i = gr1 >> 11, n1i = gr1 & 2047;
        uint32_t* o0 = dst + ((size_t)(b0i * H + h) * N + n0i) * DQK;
        uint32_t* o1 = dst + ((size_t)(b1i * H + h) * N + n1i) * DQK;
#pragma unroll
        for (int nt = 0; nt < 16; nt++) {
            const int col = wc * 128 + nt * 8 + 2 * tg;
            *(uint2*)(o0 + col) = make_uint2(f2tf32(acc[nt][0] * sc0), f2tf32(acc[nt][1] * sc0));
            *(uint2*)(o1 + col) = make_uint2(f2tf32(acc[nt][2] * sc1), f2tf32(acc[nt][3] * sc1));
        }
    }
}

// ---------------------------------------------------------------------------
// Kernel 2: attention (R13-exact except O stored as tf32 bits).
// CTA = 64 queries of one (b,h); 64-key tiles, 32 iters.
// V double-buffered; K prefetched after S-phase (overlaps PV).
// ---------------------------------------------------------------------------
#define ATT_QO   0                      // 64 x 260 u32 = 66560 B
#define ATT_KO   66560                  // 64 x 260 u32 = 66560 B
#define ATT_VO   133120                 // 2 x (64 x 136 u32 = 34816 B)
#define ATT_PO   202752                 // 64 x 68 u32 = 17408 B
#define ATT_RSO  220160                 // 128 floats = 512 B
#define ATT_SMEM 220672

__global__ __launch_bounds__(256) void attn_mma_kernel()
{
    extern __shared__ char smem[];
    const uint32_t sbase = smem_u32(smem);
    uint32_t* Qu = (uint32_t*)(smem + ATT_QO);
    uint32_t* Ku = (uint32_t*)(smem + ATT_KO);
    uint32_t* Pu = (uint32_t*)(smem + ATT_PO);
    float* rsPart = (float*)(smem + ATT_RSO);

    const int nt_blk = blockIdx.x;
    const int h  = blockIdx.y;
    const int b  = blockIdx.z;
    const int tid = threadIdx.x;
    const int wid = tid >> 5;
    const int lane = tid & 31;
    const int wr = wid & 3;
    const int wc = wid >> 2;
    const int qr = wr * 16 + (lane >> 2);
    const int tg = lane & 3;

    const uint32_t* qsrc = g_qn + ((size_t)(b * H + h) * N + nt_blk * 64) * DQK;
    const uint32_t* ksrc = g_kn + ((size_t)(b * H + h) * M) * DQK;
    const uint32_t* vsrc = g_vc + (size_t)b * M * C + h * DV;

    auto issue_k = [&](int mt) {
        const uint32_t kd = sbase + ATT_KO;
        const uint32_t* s = ksrc + (size_t)mt * 64 * DQK;
#pragma unroll
        for (int t = 0; t < 16; t++) {
            int i = tid + t * 256;
            int r = i >> 6, c = i & 63;
            CPA(kd + (uint32_t)(r * 1040 + c * 16), s + (size_t)r * DQK + c * 4);
        }
        CP_COMMIT();
    };
    auto issue_v = [&](int mt, int bi) {
        const uint32_t vd = sbase + ATT_VO + bi * 34816;
        const uint32_t* s = vsrc + (size_t)(mt * 64) * C;
#pragma unroll
        for (int t = 0; t < 8; t++) {
            int i = tid + t * 256;
            int r = i >> 5, c = i & 31;
            CPA(vd + (uint32_t)(r * 544 + c * 16), s + (size_t)r * C + c * 4);
        }
        CP_COMMIT();
    };

    // prologue: Q + K0 + V0
    {
        const uint32_t qd = sbase + ATT_QO;
#pragma unroll
        for (int t = 0; t < 16; t++) {
            int i = tid + t * 256;
            int r = i >> 6, c = i & 63;
            CPA(qd + (uint32_t)(r * 1040 + c * 16), qsrc + (size_t)r * DQK + c * 4);
        }
        CP_COMMIT();
    }
    issue_k(0);
    issue_v(0, 0);
    CP_WAIT0();
    __syncthreads();

    float o_acc[8][4];
#pragma unroll
    for (int i = 0; i < 8; i++)
#pragma unroll
        for (int j = 0; j < 4; j++) o_acc[i][j] = 0.f;
    float rsum0 = 0.f, rsum1 = 0.f;

    const float SCALE = 0.08838834764831845f;  // 1/sqrt(128)
    const float SMAX  = 11.313708498984761f;   // sqrt(128)

    for (int mt = 0; mt < M / 64; mt++) {
        const int cur = mt & 1;
        if (mt + 1 < M / 64) issue_v(mt + 1, cur ^ 1);   // overlaps S-phase

        // ---- S = Q K^T : warp tile 16 rows x 32 cols, k = 256 ----
        float s[4][4];
#pragma unroll
        for (int i = 0; i < 4; i++)
#pragma unroll
            for (int j = 0; j < 4; j++) s[i][j] = 0.f;
#pragma unroll
        for (int ks = 0; ks < 32; ks++) {
            const int c = ks * 8 + tg;
            uint32_t a0 = Qu[qr * 260 + c];
            uint32_t a1 = Qu[(qr + 8) * 260 + c];
            uint32_t a2 = Qu[qr * 260 + c + 4];
            uint32_t a3 = Qu[(qr + 8) * 260 + c + 4];
#pragma unroll
            for (int nt = 0; nt < 4; nt++) {
                int n0 = wc * 32 + nt * 8 + (lane >> 2);
                uint32_t b0 = Ku[n0 * 260 + c];
                uint32_t b1 = Ku[n0 * 260 + c + 4];
                mma_tf32(s[nt], a0, a1, a2, a3, b0, b1);
            }
        }

        // ---- softmax epilogue -> P (tf32) in smem ----
#pragma unroll
        for (int nt = 0; nt < 4; nt++) {
            float p0 = __expf(fmaf(s[nt][0], SCALE, -SMAX));
            float p1 = __expf(fmaf(s[nt][1], SCALE, -SMAX));
            float p2 = __expf(fmaf(s[nt][2], SCALE, -SMAX));
            float p3 = __expf(fmaf(s[nt][3], SCALE, -SMAX));
            rsum0 += p0 + p1;
            rsum1 += p2 + p3;
            const int col = wc * 32 + nt * 8 + 2 * tg;
            *(uint2*)(Pu + qr * 68 + col) = make_uint2(f2tf32(p0), f2tf32(p1));
            *(uint2*)(Pu + (qr + 8) * 68 + col) = make_uint2(f2tf32(p2), f2tf32(p3));
        }
        __syncthreads();                          // K free, P visible

        if (mt + 1 < M / 64) issue_k(mt + 1);     // overlaps PV

        // ---- O += P V : warp tile 16 rows x 64 cols, k = 64 ----
        const uint32_t* Vu = (const uint32_t*)(smem + ATT_VO + cur * 34816);
#pragma unroll
        for (int ks = 0; ks < 8; ks++) {
            const int c = ks * 8 + tg;
            uint32_t a0 = Pu[qr * 68 + c];
            uint32_t a1 = Pu[(qr + 8) * 68 + c];
            uint32_t a2 = Pu[qr * 68 + c + 4];
            uint32_t a3 = Pu[(qr + 8) * 68 + c + 4];
#pragma unroll
            for (int nt = 0; nt < 8; nt++) {
                int n0 = wc * 64 + nt * 8 + (lane >> 2);
                uint32_t b0 = Vu[c * 136 + n0];
                uint32_t b1 = Vu[(c + 4) * 136 + n0];
                mma_tf32(o_acc[nt], a0, a1, a2, a3, b0, b1);
            }
        }
        CP_WAIT0();
        __syncthreads();
    }

    // ---- row-sum reduction: quad, then across the two wc halves ----
#pragma unroll
    for (int o = 1; o < 4; o <<= 1) {
        rsum0 += __shfl_xor_sync(0xffffffffu, rsum0, o);
        rsum1 += __shfl_xor_sync(0xffffffffu, rsum1, o);
    }
    if (tg == 0) {
        rsPart[wc * 64 + qr] = rsum0;
        rsPart[wc * 64 + qr + 8] = rsum1;
    }
    __syncthreads();
    const float inv0 = 1.f / (rsPart[qr] + rsPart[64 + qr]);
    const float inv1 = 1.f / (rsPart[qr + 8] + rsPart[64 + qr + 8]);

    // ---- write O (tf32 bits, coalesced uint2) ----
    {
        const int n0g = nt_blk * 64 + qr;
        uint32_t* o0 = g_o + ((size_t)(b * N + n0g)) * C + h * DV;
        uint32_t* o1 = g_o + ((size_t)(b * N + n0g + 8)) * C + h * DV;
#pragma unroll
        for (int nt = 0; nt < 8; nt++) {
            const int col = wc * 64 + nt * 8 + 2 * tg;
            *(uint2*)(o0 + col) = make_uint2(f2tf32(o_acc[nt][0] * inv0), f2tf32(o_acc[nt][1] * inv0));
            *(uint2*)(o1 + col) = make_uint2(f2tf32(o_acc[nt][2] * inv1), f2tf32(o_acc[nt][3] * inv1));
        }
    }
}

// ---------------------------------------------------------------------------
// Kernel 3: output projection, tf32 mma, cp.async double-buffered.
// CTA = 64 rows x 256 cols; k = 512 in 8 chunks; output fp32.
// ---------------------------------------------------------------------------
__global__ __launch_bounds__(256) void proj_tc_kernel(float* __restrict__ out)
{
    extern __shared__ char smem[];
    const uint32_t sbase = smem_u32(smem);

    const int r0 = blockIdx.x * 64;
    const int c0 = blockIdx.y * 256;
    const int tid = threadIdx.x;
    const int wid = tid >> 5;
    const int lane = tid & 31;
    const int wr = wid & 3;
    const int wc = wid >> 2;
    const int qr = wr * 16 + (lane >> 2);
    const int tg = lane & 3;

    const uint32_t* abase = g_o + (size_t)r0 * C;
    const uint32_t* wbase = g_wp + (size_t)c0 * C;

    auto issue = [&](int kc, int bi) {
        const uint32_t xd = sbase + QKV_XB(bi);
        const uint32_t wd = sbase + QKV_WB(bi);
#pragma unroll
        for (int t = 0; t < 4; t++) {
            int i = tid + t * 256;
            int r = i >> 4, c = i & 15;
            CPA(xd + (uint32_t)(r * 272 + c * 16), abase + (size_t)r * C + kc * 64 + c * 4);
        }
#pragma unroll
        for (int t = 0; t < 16; t++) {
            int i = tid + t * 256;
            int r = i >> 4, c = i & 15;
            CPA(wd + (uint32_t)(r * 272 + c * 16), wbase + (size_t)r * C + kc * 64 + c * 4);
        }
        CP_COMMIT();
    };

    float acc[16][4];
#pragma unroll
    for (int i = 0; i < 16; i++)
#pragma unroll
        for (int j = 0; j < 4; j++) acc[i][j] = 0.f;

    issue(0, 0);
    for (int kc = 0; kc < 8; kc++) {
        if (kc < 7) issue(kc + 1, (kc + 1) & 1);
        if (kc < 7) { CP_WAIT1(); } else { CP_WAIT0(); }
        __syncthreads();
        const uint32_t* Xu = (const uint32_t*)(smem + QKV_XB(kc & 1));
        const uint32_t* Wu = (const uint32_t*)(smem + QKV_WB(kc & 1));
#pragma unroll
        for (int ks = 0; ks < 8; ks++) {
            const int c = ks * 8 + tg;
            uint32_t a0 = Xu[qr * 68 + c];
            uint32_t a1 = Xu[(qr + 8) * 68 + c];
            uint32_t a2 = Xu[qr * 68 + c + 4];
            uint32_t a3 = Xu[(qr + 8) * 68 + c + 4];
#pragma unroll
            for (int nt = 0; nt < 16; nt++) {
                int n0 = wc * 128 + nt * 8 + (lane >> 2);
                uint32_t b0 = Wu[n0 * 68 + c];
                uint32_t b1 = Wu[n0 * 68 + c + 4];
                mma_tf32(acc[nt], a0, a1, a2, a3, b0, b1);
            }
        }
        __syncthreads();
    }

    {
        float* o0 = out + (size_t)(r0 + qr) * C + c0;
        float* o1 = out + (size_t)(r0 + qr + 8) * C + c0;
#pragma unroll
        for (int nt = 0; nt < 16; nt++) {
            const int col = wc * 128 + nt * 8 + 2 * tg;
            *(float2*)(o0 + col) = make_float2(acc[nt][0], acc[nt][1]);
            *(float2*)(o1 + col) = make_float2(acc[nt][2], acc[nt][3]);
        }
    }
}

// ---------------------------------------------------------------------------
extern "C" void kernel_launch(void* const* d_in, const int* in_sizes, int n_in,
                              void* d_out, int out_size)
{
    const float* x      = (const float*)d_in[0];
    const float* ctx    = (const float*)d_in[1];
    const float* Wqkv   = (const float*)d_in[2];
    const float* Wproj  = (const float*)d_in[3];
    const float* radius = (const float*)d_in[4];
    float* out = (float*)d_out;

    (void)in_sizes; (void)n_in; (void)out_size;

    cudaFuncSetAttribute(qkv_mma_kernel,
                         cudaFuncAttributeMaxDynamicSharedMemorySize, QKV_SMEM);
    cudaFuncSetAttribute(attn_mma_kernel,
                         cudaFuncAttributeMaxDynamicSharedMemorySize, ATT_SMEM);
    cudaFuncSetAttribute(proj_tc_kernel,
                         cudaFuncAttributeMaxDynamicSharedMemorySize, QKV_SMEM);

    uint32_t* d_xs; cudaGetSymbolAddress((void**)&d_xs, g_xs);
    uint32_t* d_vc; cudaGetSymbolAddress((void**)&d_vc, g_vc);
    uint32_t* d_wq; cudaGetSymbolAddress((void**)&d_wq, g_wq);
    uint32_t* d_wp; cudaGetSymbolAddress((void**)&d_wp, g_wp);

    // pre-pass: fp32 -> tf32 bits (plain coalesced layouts)
    cvt_kernel<<<(B * N * C / 4) / 256, 256>>>(x, d_xs);
    cvt_kernel<<<(B * M * C / 4) / 256, 256>>>(ctx, d_vc);
    cvt_kernel<<<(2 * C * C / 4) / 256, 256>>>(Wqkv, d_wq);
    cvt_kernel<<<(C * C / 4) / 256, 256>>>(Wproj, d_wp);

    // 1) QKV projection + per-head L2 norm (tf32-bit outputs)
    qkv_mma_kernel<<<dim3((B * N) / 64, H, 2), 256, QKV_SMEM>>>(radius);

    // 2) attention per (b,h), 64-query tiles, cp.async overlapped
    attn_mma_kernel<<<dim3(N / 64, H, B), 256, ATT_SMEM>>>();

    // 3) output projection (tf32 mma, cp.async double-buffered)
    proj_tc_kernel<<<dim3((B * N) / 64, C / 256), 256, QKV_SMEM>>>(out);
}

// round 15
// speedup vs baseline: 1.9447x; 1.1223x over previous
#include <cuda_runtime.h>
#include <math.h>
#include <stdint.h>

#define B 4
#define N 2048
#define M 2048
#define C 512
#define H 4
#define DV 128
#define DQK 256

// scratch: tf32-bits payloads in PLAIN coalesced layouts
__device__ __align__(16) uint32_t g_xs[B * N * C];         // x (tf32 bits)
__device__ __align__(16) uint32_t g_vc[B * M * C];         // ctx (tf32 bits)
__device__ __align__(16) uint32_t g_wq[2 * C * C];         // Wqkv (tf32 bits)
__device__ __align__(16) uint32_t g_wp[C * C];             // Wproj (tf32 bits)
__device__ __align__(16) uint32_t g_qn[B * H * N * DQK];   // normed Q (tf32 bits)
__device__ __align__(16) uint32_t g_kn[B * H * M * DQK];   // normed K (tf32 bits)
__device__ __align__(16) uint32_t g_o [B * N * C];         // attn out (tf32 bits)

// ============================================================================
// helpers
// ============================================================================
__device__ __forceinline__ uint32_t f2tf32(float f) {
    uint32_t u;
    asm("cvt.rna.tf32.f32 %0, %1;" : "=r"(u) : "f"(f));
    return u;
}
__device__ __forceinline__ uint4 cvt4(float4 v) {
    uint4 u;
    u.x = f2tf32(v.x); u.y = f2tf32(v.y); u.z = f2tf32(v.z); u.w = f2tf32(v.w);
    return u;
}
__device__ __forceinline__ void mma_tf32(float* c,
                                         uint32_t a0, uint32_t a1, uint32_t a2, uint32_t a3,
                                         uint32_t b0, uint32_t b1) {
    asm volatile(
        "mma.sync.aligned.m16n8k8.row.col.f32.tf32.tf32.f32 "
        "{%0,%1,%2,%3}, {%4,%5,%6,%7}, {%8,%9}, {%0,%1,%2,%3};"
        : "+f"(c[0]), "+f"(c[1]), "+f"(c[2]), "+f"(c[3])
        : "r"(a0), "r"(a1), "r"(a2), "r"(a3), "r"(b0), "r"(b1));
}
__device__ __forceinline__ uint32_t smem_u32(const void* p) {
    uint32_t a;
    asm("{ .reg .u64 t; cvta.to.shared.u64 t, %1; cvt.u32.u64 %0, t; }" : "=r"(a) : "l"(p));
    return a;
}
#define CPA(d, s) asm volatile("cp.async.ca.shared.global [%0], [%1], 16;" :: "r"(d), "l"(s))
#define CP_COMMIT() asm volatile("cp.async.commit_group;" ::: "memory")
#define CP_WAIT0()  asm volatile("cp.async.wait_group 0;" ::: "memory")
#define CP_WAIT1()  asm volatile("cp.async.wait_group 1;" ::: "memory")

// ---------------------------------------------------------------------------
// Pre-pass: fp32 -> tf32 bits (plain layout, coalesced)
// ---------------------------------------------------------------------------
__global__ __launch_bounds__(256) void cvt_kernel(
    const float* __restrict__ src, uint32_t* __restrict__ dst)
{
    const size_t idx = (size_t)(blockIdx.x * 256 + threadIdx.x) * 4;
    float4 v = *(const float4*)(src + idx);
    *(uint4*)(dst + idx) = cvt4(v);
}

// ---------------------------------------------------------------------------
// Kernel 1: fused QKV projection + per-head L2 norm * radius (R14-exact).
// ---------------------------------------------------------------------------
#define QKV_XB(i)  ((i) * 17408)             // 2 x (64 x 68 u32)
#define QKV_WB(i)  (34816 + (i) * 69632)     // 2 x (256 x 68 u32)
#define QKV_SS     174080                    // 2 x 64 floats
#define QKV_SMEM   174592

__global__ __launch_bounds__(256) void qkv_mma_kernel(const float* __restrict__ radius)
{
    extern __shared__ char smem[];
    const uint32_t sbase = smem_u32(smem);
    float* ssPart = (float*)(smem + QKV_SS);

    const uint32_t* Asrc = (blockIdx.z == 0) ? g_xs : g_vc;
    uint32_t* dst = (blockIdx.z == 0) ? g_qn : g_kn;
    const int h  = blockIdx.y;
    const int r0 = blockIdx.x * 64;
    const int tid = threadIdx.x;
    const int wid = tid >> 5;
    const int lane = tid & 31;
    const int wr = wid & 3;
    const int wc = wid >> 2;
    const int qr = wr * 16 + (lane >> 2);
    const int tg = lane & 3;

    const uint32_t* abase = Asrc + (size_t)r0 * C;
    const uint32_t* wbase = g_wq + (size_t)(h * 256) * C;

    auto issue = [&](int kc, int bi) {
        const uint32_t xd = sbase + QKV_XB(bi);
        const uint32_t wd = sbase + QKV_WB(bi);
#pragma unroll
        for (int t = 0; t < 4; t++) {
            int i = tid + t * 256;
            int r = i >> 4, c = i & 15;
            CPA(xd + (uint32_t)(r * 272 + c * 16), abase + (size_t)r * C + kc * 64 + c * 4);
        }
#pragma unroll
        for (int t = 0; t < 16; t++) {
            int i = tid + t * 256;
            int r = i >> 4, c = i & 15;
            CPA(wd + (uint32_t)(r * 272 + c * 16), wbase + (size_t)r * C + kc * 64 + c * 4);
        }
        CP_COMMIT();
    };

    float acc[16][4];
#pragma unroll
    for (int i = 0; i < 16; i++)
#pragma unroll
        for (int j = 0; j < 4; j++) acc[i][j] = 0.f;

    issue(0, 0);
    for (int kc = 0; kc < 8; kc++) {
        if (kc < 7) issue(kc + 1, (kc + 1) & 1);
        if (kc < 7) { CP_WAIT1(); } else { CP_WAIT0(); }
        __syncthreads();
        const uint32_t* Xu = (const uint32_t*)(smem + QKV_XB(kc & 1));
        const uint32_t* Wu = (const uint32_t*)(smem + QKV_WB(kc & 1));
#pragma unroll
        for (int ks = 0; ks < 8; ks++) {
            const int c = ks * 8 + tg;
            uint32_t a0 = Xu[qr * 68 + c];
            uint32_t a1 = Xu[(qr + 8) * 68 + c];
            uint32_t a2 = Xu[qr * 68 + c + 4];
            uint32_t a3 = Xu[(qr + 8) * 68 + c + 4];
#pragma unroll
            for (int nt = 0; nt < 16; nt++) {
                int n0 = wc * 128 + nt * 8 + (lane >> 2);
                uint32_t b0 = Wu[n0 * 68 + c];
                uint32_t b1 = Wu[n0 * 68 + c + 4];
                mma_tf32(acc[nt], a0, a1, a2, a3, b0, b1);
            }
        }
        __syncthreads();
    }

    float ss0 = 0.f, ss1 = 0.f;
#pragma unroll
    for (int nt = 0; nt < 16; nt++) {
        ss0 += acc[nt][0] * acc[nt][0] + acc[nt][1] * acc[nt][1];
        ss1 += acc[nt][2] * acc[nt][2] + acc[nt][3] * acc[nt][3];
    }
#pragma unroll
    for (int o = 1; o < 4; o <<= 1) {
        ss0 += __shfl_xor_sync(0xffffffffu, ss0, o);
        ss1 += __shfl_xor_sync(0xffffffffu, ss1, o);
    }
    if (tg == 0) {
        ssPart[wc * 64 + qr] = ss0;
        ssPart[wc * 64 + qr + 8] = ss1;
    }
    __syncthreads();

    const float rad = radius[h];
    const float sc0 = rad / fmaxf(sqrtf(ssPart[qr] + ssPart[64 + qr]), 1e-12f);
    const float sc1 = rad / fmaxf(sqrtf(ssPart[qr + 8] + ssPart[64 + qr + 8]), 1e-12f);

    {
        const int gr0 = r0 + qr;
        const int b0i = gr0 >> 11, n0i = gr0 & 2047;
        const int gr1 = gr0 + 8;
        const int b1i = gr1 >> 11, n1i = gr1 & 2047;
        uint32_t* o0 = dst + ((size_t)(b0i * H + h) * N + n0i) * DQK;
        uint32_t* o1 = dst + ((size_t)(b1i * H + h) * N + n1i) * DQK;
#pragma unroll
        for (int nt = 0; nt < 16; nt++) {
            const int col = wc * 128 + nt * 8 + 2 * tg;
            *(uint2*)(o0 + col) = make_uint2(f2tf32(acc[nt][0] * sc0), f2tf32(acc[nt][1] * sc0));
            *(uint2*)(o1 + col) = make_uint2(f2tf32(acc[nt][2] * sc1), f2tf32(acc[nt][3] * sc1));
        }
    }
}

// ---------------------------------------------------------------------------
// Kernel 2: attention, register-resident P (flash-attention style).
// CTA = 128 queries of one (b,h), 8 warps, warp owns 16 rows end-to-end.
// 32-key tiles, 64 iters. S: warp m16 x n32 (4 n8-tiles x 32 ksteps).
// P stays in registers; C-layout -> A-fragment via shfl. PV: m16 x n128, k32.
// K double-buffered; V single-buffered (loaded during next S).
// ---------------------------------------------------------------------------
#define AT_Q    0                     // 128 x 260 u32 = 133120 B
#define AT_K    133120                // 2 x (32 x 260 u32 = 33280 B)
#define AT_V    199680                // 32 x 136 u32 = 17408 B
#define AT_SMEM 217088

__global__ __launch_bounds__(256) void attn_mma_kernel()
{
    extern __shared__ char smem[];
    const uint32_t sbase = smem_u32(smem);
    uint32_t* Qu = (uint32_t*)(smem + AT_Q);
    uint32_t* Vu = (uint32_t*)(smem + AT_V);

    const int nt_blk = blockIdx.x;          // 0..15 (128-query tiles)
    const int h  = blockIdx.y;
    const int b  = blockIdx.z;
    const int tid = threadIdx.x;
    const int wid = tid >> 5;
    const int lane = tid & 31;
    const int rq = lane >> 2, tg = lane & 3;
    const int qr = wid * 16 + rq;           // warp's query rows: qr, qr+8

    const uint32_t* qsrc = g_qn + ((size_t)(b * H + h) * N + nt_blk * 128) * DQK;
    const uint32_t* ksrc = g_kn + ((size_t)(b * H + h) * M) * DQK;
    const uint32_t* vsrc = g_vc + (size_t)b * M * C + h * DV;

    auto issue_k = [&](int mt, int bi) {
        const uint32_t kd = sbase + AT_K + bi * 33280;
        const uint32_t* s = ksrc + (size_t)(mt * 32) * DQK;
#pragma unroll
        for (int t = 0; t < 8; t++) {
            int i = tid + t * 256;
            int r = i >> 6, c = i & 63;                  // 32 rows x 64 chunks
            CPA(kd + (uint32_t)(r * 1040 + c * 16), s + (size_t)r * DQK + c * 4);
        }
        CP_COMMIT();
    };
    auto issue_v = [&](int mt) {
        const uint32_t vd = sbase + AT_V;
        const uint32_t* s = vsrc + (size_t)(mt * 32) * C;
#pragma unroll
        for (int t = 0; t < 4; t++) {
            int i = tid + t * 256;
            int r = i >> 5, c = i & 31;                  // 32 rows x 32 chunks
            CPA(vd + (uint32_t)(r * 544 + c * 16), s + (size_t)r * C + c * 4);
        }
        CP_COMMIT();
    };

    // prologue: Q + K0 + V0
    {
        const uint32_t qd = sbase + AT_Q;
#pragma unroll
        for (int t = 0; t < 32; t++) {
            int i = tid + t * 256;
            int r = i >> 6, c = i & 63;                  // 128 rows x 64 chunks
            CPA(qd + (uint32_t)(r * 1040 + c * 16), qsrc + (size_t)r * DQK + c * 4);
        }
        CP_COMMIT();
    }
    issue_k(0, 0);
    issue_v(0);
    CP_WAIT0();
    __syncthreads();

    float o_acc[16][4];
#pragma unroll
    for (int j = 0; j < 16; j++)
#pragma unroll
        for (int k = 0; k < 4; k++) o_acc[j][k] = 0.f;
    float rsum0 = 0.f, rsum1 = 0.f;

    const float SCALE = 0.08838834764831845f;  // 1/sqrt(128)
    const float SMAX  = 11.313708498984761f;   // sqrt(128)

    for (int mt = 0; mt < M / 32; mt++) {
        const int kcur = mt & 1;
        if (mt + 1 < M / 32) issue_k(mt + 1, kcur ^ 1);   // loads during S+PV

        // ---- S = Q K^T : warp m16 x n32, k = 256 ----
        const uint32_t* Ku = (const uint32_t*)(smem + AT_K + kcur * 33280);
        float p[4][4];
#pragma unroll
        for (int a = 0; a < 4; a++)
#pragma unroll
            for (int j = 0; j < 4; j++) p[a][j] = 0.f;
#pragma unroll
        for (int ks = 0; ks < 32; ks++) {
            const int c = ks * 8 + tg;
            uint32_t a0 = Qu[qr * 260 + c];
            uint32_t a1 = Qu[(qr + 8) * 260 + c];
            uint32_t a2 = Qu[qr * 260 + c + 4];
            uint32_t a3 = Qu[(qr + 8) * 260 + c + 4];
#pragma unroll
            for (int nt = 0; nt < 4; nt++) {
                int n0 = nt * 8 + rq;
                uint32_t b0 = Ku[n0 * 260 + c];
                uint32_t b1 = Ku[n0 * 260 + c + 4];
                mma_tf32(p[nt], a0, a1, a2, a3, b0, b1);
            }
        }

        // ---- softmax (registers) ----
#pragma unroll
        for (int nt = 0; nt < 4; nt++) {
            p[nt][0] = __expf(fmaf(p[nt][0], SCALE, -SMAX));
            p[nt][1] = __expf(fmaf(p[nt][1], SCALE, -SMAX));
            p[nt][2] = __expf(fmaf(p[nt][2], SCALE, -SMAX));
            p[nt][3] = __expf(fmaf(p[nt][3], SCALE, -SMAX));
            rsum0 += p[nt][0] + p[nt][1];
            rsum1 += p[nt][2] + p[nt][3];
        }

        // wait V_mt ready (mt=0: already; else completes V group, K' may pend)
        if (mt + 1 < M / 32) { CP_WAIT1(); } else { CP_WAIT0(); }
        __syncthreads();

        // ---- PV: C-layout P -> A-frag via shfl; warp m16 x n128, k = 32 ----
        const int src0 = (lane & 0x1c) + (tg >> 1);
        const int src1 = src0 + 2;
        const bool odd = (tg & 1) != 0;
#pragma unroll
        for (int nt = 0; nt < 4; nt++) {
            float x0 = __shfl_sync(0xffffffffu, p[nt][0], src0);
            float x1 = __shfl_sync(0xffffffffu, p[nt][1], src0);
            float y0 = __shfl_sync(0xffffffffu, p[nt][2], src0);
            float y1 = __shfl_sync(0xffffffffu, p[nt][3], src0);
            float z0 = __shfl_sync(0xffffffffu, p[nt][0], src1);
            float z1 = __shfl_sync(0xffffffffu, p[nt][1], src1);
            float w0 = __shfl_sync(0xffffffffu, p[nt][2], src1);
            float w1 = __shfl_sync(0xffffffffu, p[nt][3], src1);
            uint32_t a0 = f2tf32(odd ? x1 : x0);
            uint32_t a1 = f2tf32(odd ? y1 : y0);
            uint32_t a2 = f2tf32(odd ? z1 : z0);
            uint32_t a3 = f2tf32(odd ? w1 : w0);
            const int k0 = (nt * 8 + tg) * 136;
            const int k1 = (nt * 8 + tg + 4) * 136;
#pragma unroll
            for (int j = 0; j < 16; j++) {
                uint32_t b0 = Vu[k0 + j * 8 + rq];
                uint32_t b1 = Vu[k1 + j * 8 + rq];
                mma_tf32(o_acc[j], a0, a1, a2, a3, b0, b1);
            }
        }
        __syncthreads();                     // Vu (and Ku[kcur]) consumed

        if (mt + 1 < M / 32) {
            issue_v(mt + 1);                 // overwrites Vu, loads during next S
            CP_WAIT1();                      // completes K_{mt+1}
            __syncthreads();
        }
    }

    // ---- normalize (quad-reduce: each warp saw ALL keys for its rows) ----
#pragma unroll
    for (int o = 1; o < 4; o <<= 1) {
        rsum0 += __shfl_xor_sync(0xffffffffu, rsum0, o);
        rsum1 += __shfl_xor_sync(0xffffffffu, rsum1, o);
    }
    const float inv0 = 1.f / rsum0;
    const float inv1 = 1.f / rsum1;

    // ---- write O (tf32 bits, coalesced uint2) ----
    {
        const int n0g = nt_blk * 128 + qr;
        uint32_t* o0 = g_o + ((size_t)(b * N + n0g)) * C + h * DV;
        uint32_t* o1 = o0 + (size_t)8 * C;
#pragma unroll
        for (int j = 0; j < 16; j++) {
            const int col = j * 8 + 2 * tg;
            *(uint2*)(o0 + col) = make_uint2(f2tf32(o_acc[j][0] * inv0), f2tf32(o_acc[j][1] * inv0));
            *(uint2*)(o1 + col) = make_uint2(f2tf32(o_acc[j][2] * inv1), f2tf32(o_acc[j][3] * inv1));
        }
    }
}

// ---------------------------------------------------------------------------
// Kernel 3: output projection, tf32 mma, cp.async double-buffered (R14-exact).
// ---------------------------------------------------------------------------
__global__ __launch_bounds__(256) void proj_tc_kernel(float* __restrict__ out)
{
    extern __shared__ char smem[];
    const uint32_t sbase = smem_u32(smem);

    const int r0 = blockIdx.x * 64;
    const int c0 = blockIdx.y * 256;
    const int tid = threadIdx.x;
    const int wid = tid >> 5;
    const int lane = tid & 31;
    const int wr = wid & 3;
    const int wc = wid >> 2;
    const int qr = wr * 16 + (lane >> 2);
    const int tg = lane & 3;

    const uint32_t* abase = g_o + (size_t)r0 * C;
    const uint32_t* wbase = g_wp + (size_t)c0 * C;

    auto issue = [&](int kc, int bi) {
        const uint32_t xd = sbase + QKV_XB(bi);
        const uint32_t wd = sbase + QKV_WB(bi);
#pragma unroll
        for (int t = 0; t < 4; t++) {
            int i = tid + t * 256;
            int r = i >> 4, c = i & 15;
            CPA(xd + (uint32_t)(r * 272 + c * 16), abase + (size_t)r * C + kc * 64 + c * 4);
        }
#pragma unroll
        for (int t = 0; t < 16; t++) {
            int i = tid + t * 256;
            int r = i >> 4, c = i & 15;
            CPA(wd + (uint32_t)(r * 272 + c * 16), wbase + (size_t)r * C + kc * 64 + c * 4);
        }
        CP_COMMIT();
    };

    float acc[16][4];
#pragma unroll
    for (int i = 0; i < 16; i++)
#pragma unroll
        for (int j = 0; j < 4; j++) acc[i][j] = 0.f;

    issue(0, 0);
    for (int kc = 0; kc < 8; kc++) {
        if (kc < 7) issue(kc + 1, (kc + 1) & 1);
        if (kc < 7) { CP_WAIT1(); } else { CP_WAIT0(); }
        __syncthreads();
        const uint32_t* Xu = (const uint32_t*)(smem + QKV_XB(kc & 1));
        const uint32_t* Wu = (const uint32_t*)(smem + QKV_WB(kc & 1));
#pragma unroll
        for (int ks = 0; ks < 8; ks++) {
            const int c = ks * 8 + tg;
            uint32_t a0 = Xu[qr * 68 + c];
            uint32_t a1 = Xu[(qr + 8) * 68 + c];
            uint32_t a2 = Xu[qr * 68 + c + 4];
            uint32_t a3 = Xu[(qr + 8) * 68 + c + 4];
#pragma unroll
            for (int nt = 0; nt < 16; nt++) {
                int n0 = wc * 128 + nt * 8 + (lane >> 2);
                uint32_t b0 = Wu[n0 * 68 + c];
                uint32_t b1 = Wu[n0 * 68 + c + 4];
                mma_tf32(acc[nt], a0, a1, a2, a3, b0, b1);
            }
        }
        __syncthreads();
    }

    {
        float* o0 = out + (size_t)(r0 + qr) * C + c0;
        float* o1 = out + (size_t)(r0 + qr + 8) * C + c0;
#pragma unroll
        for (int nt = 0; nt < 16; nt++) {
            const int col = wc * 128 + nt * 8 + 2 * tg;
            *(float2*)(o0 + col) = make_float2(acc[nt][0], acc[nt][1]);
            *(float2*)(o1 + col) = make_float2(acc[nt][2], acc[nt][3]);
        }
    }
}

// ---------------------------------------------------------------------------
extern "C" void kernel_launch(void* const* d_in, const int* in_sizes, int n_in,
                              void* d_out, int out_size)
{
    const float* x      = (const float*)d_in[0];
    const float* ctx    = (const float*)d_in[1];
    const float* Wqkv   = (const float*)d_in[2];
    const float* Wproj  = (const float*)d_in[3];
    const float* radius = (const float*)d_in[4];
    float* out = (float*)d_out;

    (void)in_sizes; (void)n_in; (void)out_size;

    cudaFuncSetAttribute(qkv_mma_kernel,
                         cudaFuncAttributeMaxDynamicSharedMemorySize, QKV_SMEM);
    cudaFuncSetAttribute(attn_mma_kernel,
                         cudaFuncAttributeMaxDynamicSharedMemorySize, AT_SMEM);
    cudaFuncSetAttribute(proj_tc_kernel,
                         cudaFuncAttributeMaxDynamicSharedMemorySize, QKV_SMEM);

    uint32_t* d_xs; cudaGetSymbolAddress((void**)&d_xs, g_xs);
    uint32_t* d_vc; cudaGetSymbolAddress((void**)&d_vc, g_vc);
    uint32_t* d_wq; cudaGetSymbolAddress((void**)&d_wq, g_wq);
    uint32_t* d_wp; cudaGetSymbolAddress((void**)&d_wp, g_wp);

    // pre-pass: fp32 -> tf32 bits (plain coalesced layouts)
    cvt_kernel<<<(B * N * C / 4) / 256, 256>>>(x, d_xs);
    cvt_kernel<<<(B * M * C / 4) / 256, 256>>>(ctx, d_vc);
    cvt_kernel<<<(2 * C * C / 4) / 256, 256>>>(Wqkv, d_wq);
    cvt_kernel<<<(C * C / 4) / 256, 256>>>(Wproj, d_wp);

    // 1) QKV projection + per-head L2 norm (tf32-bit outputs)
    qkv_mma_kernel<<<dim3((B * N) / 64, H, 2), 256, QKV_SMEM>>>(radius);

    // 2) attention per (b,h), 128-query tiles, register-resident P
    attn_mma_kernel<<<dim3(N / 128, H, B), 256, AT_SMEM>>>();

    // 3) output projection (tf32 mma, cp.async double-buffered)
    proj_tc_kernel<<<dim3((B * N) / 64, C / 256), 256, QKV_SMEM>>>(out);
}